// round 8
// baseline (speedup 1.0000x reference)
#include <cuda_runtime.h>
#include <math.h>

#define SS 7
#define NPTS 49
#define CCH 256
#define CSPLIT 2
#define CPER (CCH / CSPLIT)

__global__ __launch_bounds__(256) void oriented_roi_align_kernel(
    const float* __restrict__ f0, const float* __restrict__ f1,
    const float* __restrict__ f2, const float* __restrict__ f3,
    const float* __restrict__ rois, const int* __restrict__ levels,
    float* __restrict__ out, int N)
{
    const int roi  = blockIdx.x >> 1;
    const int half = blockIdx.x & 1;
    const int bb   = roi / N;
    const int tid  = threadIdx.x;

    // old-path (lvl 2/3) tap tables
    __shared__ float s_w00[NPTS], s_w01[NPTS], s_w10[NPTS], s_w11[NPTS];
    __shared__ int   s_o00[NPTS], s_o01[NPTS], s_o10[NPTS], s_o11[NPTS];
    // new-path (lvl 0/1) transposed tables: [group][lane] with lane=(p&7)*4+t
    __shared__ int   s_offT[7][32];
    __shared__ float s_wT[7][32];

    const int lvl = __ldg(levels + roi);
    int H; float scale; const float* fbase;
    switch (lvl) {
        case 0:  H = 256; scale = 0.25f;     fbase = f0; break;
        case 1:  H = 128; scale = 0.125f;    fbase = f1; break;
        case 2:  H = 64;  scale = 0.0625f;   fbase = f2; break;
        default: H = 32;  scale = 0.03125f;  fbase = f3; break;
    }
    const int HW = H * H;
    const float* base = fbase + (size_t)bb * CCH * HW;
    float* op = out + (size_t)roi * CCH * NPTS;

    if (tid < NPTS) {
        const float* r = rois + (size_t)roi * 6;
        const float x = r[0], y = r[1], w = r[2], h = r[3], a = r[4], b = r[5];

        // ---- parallelogram -> rectangle (matches reference) ----
        const float d1 = sqrtf(4.f * a * a + h * h);
        const float d2 = sqrtf(w * w + 4.f * b * b);
        const float eps = 1e-6f;
        float V0x, V0y, V1x, V1y, V2x, V2y;
        if (d1 > d2) {
            const float sA = d1 / (d2 + eps);
            V0x = x + a;          V0y = y + 0.5f * h;
            V1x = (x + 0.5f * w) + (sA - 1.f) * (0.5f * w);
            V1y = (y + b)        + (sA - 1.f) * b;
            V2x = x - a;          V2y = y - 0.5f * h;
        } else {
            const float sB = d2 / (d1 + eps);
            V0x = (x + a)        + (sB - 1.f) * a;
            V0y = (y + 0.5f * h) + (sB - 1.f) * (0.5f * h);
            V1x = x + 0.5f * w;   V1y = y + b;
            V2x = (x - a)        - (sB - 1.f) * a;
            V2y = (y - 0.5f * h) - (sB - 1.f) * (0.5f * h);
        }
        const float hre = sqrtf((V1x - V0x) * (V1x - V0x) + (V1y - V0y) * (V1y - V0y));
        const float wre = sqrtf((V2x - V1x) * (V2x - V1x) + (V2y - V1y) * (V2y - V1y));
        float theta = atan2f(V1y - V2y, V1x - V2x);
        const float PI2 = 1.5707963267948966f;
        theta = fminf(fmaxf(theta, -PI2), PI2);
        const float ct = cosf(theta), st = sinf(theta);

        const int   i  = tid / SS, j = tid % SS;
        const float tj = (float)j / 6.f - 0.5f;
        const float ti = (float)i / 6.f - 0.5f;
        const float gx = wre * scale * tj;
        const float gy = hre * scale * ti;
        const float rx =  gx * ct + gy * st + x * scale;
        const float ry = -gx * st + gy * ct + y * scale;

        const float Wf  = (float)H;
        const float inv = 1.f / (float)(H - 1);
        const float gxn = rx * scale * inv * 2.f - 1.f;
        const float gyn = ry * scale * inv * 2.f - 1.f;
        const float px = ((gxn + 1.f) * Wf - 1.f) * 0.5f;
        const float py = ((gyn + 1.f) * Wf - 1.f) * 0.5f;

        const float x0f = floorf(px), y0f = floorf(py);
        const float wx = px - x0f, wy = py - y0f;
        const int x0 = min(max((int)x0f, 0), H - 1);
        const int x1 = min(x0 + 1, H - 1);
        const int y0 = min(max((int)y0f, 0), H - 1);
        const int y1 = min(y0 + 1, H - 1);

        const int o00 = y0 * H + x0, o01 = y0 * H + x1;
        const int o10 = y1 * H + x0, o11 = y1 * H + x1;
        const float w00 = (1.f - wx) * (1.f - wy);
        const float w01 = wx * (1.f - wy);
        const float w10 = (1.f - wx) * wy;
        const float w11 = wx * wy;

        s_o00[tid] = o00; s_o01[tid] = o01; s_o10[tid] = o10; s_o11[tid] = o11;
        s_w00[tid] = w00; s_w01[tid] = w01; s_w10[tid] = w10; s_w11[tid] = w11;

        const int g  = tid >> 3;
        const int li = (tid & 7) << 2;
        s_offT[g][li + 0] = o00;  s_wT[g][li + 0] = w00;
        s_offT[g][li + 1] = o01;  s_wT[g][li + 1] = w01;
        s_offT[g][li + 2] = o10;  s_wT[g][li + 2] = w10;
        s_offT[g][li + 3] = o11;  s_wT[g][li + 3] = w11;
    } else if (tid < 56) {
        // pad entries for points 49..55 (group 6, lanes 4..31)
        const int g  = tid >> 3;
        const int li = (tid & 7) << 2;
        #pragma unroll
        for (int t = 0; t < 4; t++) { s_offT[g][li + t] = 0; s_wT[g][li + t] = 0.f; }
    }
    __syncthreads();

    const int warp = tid >> 5;
    const int lane = tid & 31;
    const int cbase = half * CPER;

    if (lvl <= 1) {
        // ---- tap-per-lane path: 1 LDG covers 8 points x 4 taps of one channel ----
        const int p = (lane >> 2);           // local point within group
        const int isT0 = ((lane & 3) == 0);
        const int nItems = (CPER >> 2) * 7;  // channel-quads x 7 groups

        #pragma unroll 1
        for (int it = warp; it < nItems; it += 8) {
            const int cq = it / 7;
            const int g  = it - cq * 7;
            const int c  = cbase + (cq << 2);
            const int   off = s_offT[g][lane];
            const float wgt = s_wT[g][lane];

            const float* pl = base + (size_t)c * HW;
            float v0 = __ldg(pl + off) * wgt;
            float v1 = __ldg(pl + HW + off) * wgt;
            float v2 = __ldg(pl + 2 * HW + off) * wgt;
            float v3 = __ldg(pl + 3 * HW + off) * wgt;

            v0 += __shfl_xor_sync(0xffffffffu, v0, 1);
            v1 += __shfl_xor_sync(0xffffffffu, v1, 1);
            v2 += __shfl_xor_sync(0xffffffffu, v2, 1);
            v3 += __shfl_xor_sync(0xffffffffu, v3, 1);
            v0 += __shfl_xor_sync(0xffffffffu, v0, 2);
            v1 += __shfl_xor_sync(0xffffffffu, v1, 2);
            v2 += __shfl_xor_sync(0xffffffffu, v2, 2);
            v3 += __shfl_xor_sync(0xffffffffu, v3, 2);

            const int pt = (g << 3) + p;
            if (isT0 && pt < NPTS) {
                float* o = op + c * NPTS + pt;
                o[0]         = v0;
                o[NPTS]      = v1;
                o[2 * NPTS]  = v2;
                o[3 * NPTS]  = v3;
            }
        }
    } else {
        // ---- proven gather path (levels 2-3) ----
        const int  pA = lane;
        const bool hasB = (32 + lane) < NPTS;
        const int  pB = hasB ? 32 + lane : 0;

        const int   a00 = s_o00[pA], a01 = s_o01[pA], a10 = s_o10[pA], a11 = s_o11[pA];
        const float wa00 = s_w00[pA], wa01 = s_w01[pA], wa10 = s_w10[pA], wa11 = s_w11[pA];
        const int   b00 = s_o00[pB], b01 = s_o01[pB], b10 = s_o10[pB], b11 = s_o11[pB];
        const float wb00 = s_w00[pB], wb01 = s_w01[pB], wb10 = s_w10[pB], wb11 = s_w11[pB];

        const int cend = cbase + CPER;
        #pragma unroll 1
        for (int c = cbase + warp; c < cend; c += 16) {
            const float* pl0 = base + (size_t)c * HW;
            const float* pl1 = pl0 + (size_t)8 * HW;
            float* o0 = op + c * NPTS;
            float* o1 = o0 + 8 * NPTS;

            const float v0a00 = __ldg(pl0 + a00), v0a01 = __ldg(pl0 + a01);
            const float v0a10 = __ldg(pl0 + a10), v0a11 = __ldg(pl0 + a11);
            const float v1a00 = __ldg(pl1 + a00), v1a01 = __ldg(pl1 + a01);
            const float v1a10 = __ldg(pl1 + a10), v1a11 = __ldg(pl1 + a11);

            float v0b00 = 0.f, v0b01 = 0.f, v0b10 = 0.f, v0b11 = 0.f;
            float v1b00 = 0.f, v1b01 = 0.f, v1b10 = 0.f, v1b11 = 0.f;
            if (hasB) {
                v0b00 = __ldg(pl0 + b00); v0b01 = __ldg(pl0 + b01);
                v0b10 = __ldg(pl0 + b10); v0b11 = __ldg(pl0 + b11);
                v1b00 = __ldg(pl1 + b00); v1b01 = __ldg(pl1 + b01);
                v1b10 = __ldg(pl1 + b10); v1b11 = __ldg(pl1 + b11);
            }

            o0[pA] = v0a00 * wa00 + v0a01 * wa01 + v0a10 * wa10 + v0a11 * wa11;
            o1[pA] = v1a00 * wa00 + v1a01 * wa01 + v1a10 * wa10 + v1a11 * wa11;
            if (hasB) {
                o0[pB] = v0b00 * wb00 + v0b01 * wb01 + v0b10 * wb10 + v0b11 * wb11;
                o1[pB] = v1b00 * wb00 + v1b01 * wb01 + v1b10 * wb10 + v1b11 * wb11;
            }
        }
    }
}

extern "C" void kernel_launch(void* const* d_in, const int* in_sizes, int n_in,
                              void* d_out, int out_size) {
    const float* f0 = (const float*)d_in[0];
    const float* f1 = (const float*)d_in[1];
    const float* f2 = (const float*)d_in[2];
    const float* f3 = (const float*)d_in[3];
    const float* rois = (const float*)d_in[4];
    const int* levels = (const int*)d_in[5];
    float* out = (float*)d_out;

    const int B = in_sizes[0] / (256 * 256 * 256);
    const int total = in_sizes[5];
    const int N = total / (B > 0 ? B : 1);

    oriented_roi_align_kernel<<<total * CSPLIT, 256>>>(f0, f1, f2, f3, rois, levels, out, N);
}